// round 9
// baseline (speedup 1.0000x reference)
#include <cuda_runtime.h>
#include <math_constants.h>
#include <cstdint>

// Problem constants
constexpr int B_ = 2;
constexpr int N_ = 2048;
constexpr int C_ = 1024;
constexpr int H_ = 16;
constexpr int D_ = 64;
constexpr int M_ = B_ * N_;      // 4096 rows of x
constexpr float SCALE = 0.125f;  // D^-0.5

// Scratch (device globals; no allocation allowed)
__device__ float g_q[(size_t)B_ * H_ * N_ * D_];   // [B*H, N, D] (tf32-rounded)
__device__ float g_k[(size_t)B_ * H_ * N_ * D_];
__device__ float g_v[(size_t)B_ * H_ * N_ * D_];
__device__ float g_ao[(size_t)B_ * N_ * C_];       // attn out [B*N, C] (tf32-rounded)
__device__ float g_xr[(size_t)M_ * C_];            // x rounded to tf32
__device__ float g_wqkv[(size_t)3 * C_ * C_];      // qkv_w rounded to tf32
__device__ float g_wproj[(size_t)C_ * C_];         // proj_w rounded to tf32

// ---------------------------------------------------------------------------
// helpers
// ---------------------------------------------------------------------------
__device__ __forceinline__ unsigned f2tf(float f) {
    unsigned u;
    asm("cvt.rna.tf32.f32 %0, %1;" : "=r"(u) : "f"(f));
    return u;
}
__device__ __forceinline__ float tf32r(float f) {
    return __uint_as_float(f2tf(f));
}

__device__ __forceinline__ void mma_tf32(
    float& c0, float& c1, float& c2, float& c3,
    unsigned a0, unsigned a1, unsigned a2, unsigned a3,
    unsigned b0, unsigned b1)
{
    asm volatile(
        "mma.sync.aligned.m16n8k8.row.col.f32.tf32.tf32.f32 "
        "{%0,%1,%2,%3}, {%4,%5,%6,%7}, {%8,%9}, {%0,%1,%2,%3};"
        : "+f"(c0), "+f"(c1), "+f"(c2), "+f"(c3)
        : "r"(a0), "r"(a1), "r"(a2), "r"(a3), "r"(b0), "r"(b1));
}

__device__ __forceinline__ void cp_async16(unsigned saddr, const void* gptr) {
    asm volatile("cp.async.ca.shared.global [%0], [%1], 16;"
                 :: "r"(saddr), "l"(gptr));
}
__device__ __forceinline__ void cp_commit() {
    asm volatile("cp.async.commit_group;");
}

// ---------------------------------------------------------------------------
// Pre-pass: round fp32 buffer to tf32 (RNA) into scratch.
// ---------------------------------------------------------------------------
__global__ __launch_bounds__(256) void round_kernel(
    const float4* __restrict__ src, float4* __restrict__ dst, int n4)
{
    const int i = blockIdx.x * 256 + threadIdx.x;
    if (i < n4) {
        float4 v = src[i];
        v.x = tf32r(v.x); v.y = tf32r(v.y);
        v.z = tf32r(v.z); v.w = tf32r(v.w);
        dst[i] = v;
    }
}

// ---------------------------------------------------------------------------
// tf32 TN GEMM on pre-rounded data: C[M,N] = A @ W^T, K = 1024.
// Block 128x128x16, 8 warps (2x4), warp tile 64x32.
// 3-stage cp.async pipeline, ONE __syncthreads per chunk.
// smem: 3 stages x 2 matrices x 128 rows x 16 floats (64B rows),
// XOR-swizzled (chunk ^ ((row>>1)&3)) -> conflict-free frag LDS, 0 padding.
// Total = 49152 B = static limit.
// EPI=0: qkv + RoPE scatter (tf32-rounded).  EPI=1: bias add -> out.
// ---------------------------------------------------------------------------
constexpr int STG_BYTES = 128 * 16 * 4;   // 8192 per stage per matrix

template<int EPI>
__global__ __launch_bounds__(256) void gemm_tf32_kernel(
    const float* __restrict__ fcos, const float* __restrict__ fsin,
    const float* __restrict__ bias, float* __restrict__ out)
{
    __shared__ float As[3][128 * 16];
    __shared__ float Bs[3][128 * 16];

    const float* A = (EPI == 1) ? g_ao : g_xr;
    const float* W = (EPI == 1) ? g_wproj : g_wqkv;

    const int tid = threadIdx.x;
    const int w = tid >> 5;
    const int lane = tid & 31;
    const int g = lane >> 2;     // 0..7
    const int t = lane & 3;      // 0..3
    const int wm = w >> 2;       // 0..1
    const int wn = w & 3;        // 0..3

    const int m0 = blockIdx.y * 128;
    const int n0 = blockIdx.x * 128;

    // ---- producer mapping: thread owns row r, chunks {cb, cb+1} (16B each)
    const int r = tid >> 1;              // 0..127
    const int cb = (tid & 1) * 2;        // 0 or 2
    const int swst = (r >> 1) & 3;
    uint32_t dstA[2], dstB[2];
#pragma unroll
    for (int c = 0; c < 2; c++) {
        const uint32_t off = (uint32_t)r * 64 + (uint32_t)(((cb + c) ^ swst) << 4);
        dstA[c] = (uint32_t)__cvta_generic_to_shared((const char*)As + off);
        dstB[c] = (uint32_t)__cvta_generic_to_shared((const char*)Bs + off);
    }
    const float* agm = A + (size_t)(m0 + r) * 1024 + cb * 4;
    const float* bgm = W + (size_t)(n0 + r) * 1024 + cb * 4;

    // ---- consumer mapping constants
    const int swx = (g >> 1) & 3;        // == ((row>>1)&3) for all frag rows
    const char* cAs = (const char*)As;
    const char* cBs = (const char*)Bs;

    float acc[4][4][4];
#pragma unroll
    for (int i = 0; i < 4; i++)
#pragma unroll
        for (int j = 0; j < 4; j++)
#pragma unroll
            for (int q = 0; q < 4; q++) acc[i][j][q] = 0.f;

    // prologue: issue chunks 0 and 1
#pragma unroll
    for (int pk = 0; pk < 2; pk++) {
        const uint32_t so = (uint32_t)pk * STG_BYTES;
#pragma unroll
        for (int c = 0; c < 2; c++) {
            cp_async16(dstA[c] + so, agm + pk * 16 + c * 4);
            cp_async16(dstB[c] + so, bgm + pk * 16 + c * 4);
        }
        cp_commit();
    }

    int cstage = 0;   // stage holding chunk kt
    int pstage = 2;   // stage receiving chunk kt+2
    for (int kt = 0; kt < 64; kt++) {
        if (kt < 63) {
            asm volatile("cp.async.wait_group 1;");
        } else {
            asm volatile("cp.async.wait_group 0;");
        }
        __syncthreads();   // chunk kt visible to all; stage pstage fully consumed

        if (kt < 62) {
            const int kc = (kt + 2) * 16;
            const uint32_t so = (uint32_t)pstage * STG_BYTES;
#pragma unroll
            for (int c = 0; c < 2; c++) {
                cp_async16(dstA[c] + so, agm + kc + c * 4);
                cp_async16(dstB[c] + so, bgm + kc + c * 4);
            }
            cp_commit();
        }

        const char* sa = cAs + cstage * STG_BYTES;
        const char* sb = cBs + cstage * STG_BYTES;
#pragma unroll
        for (int ks = 0; ks < 2; ks++) {
            const uint32_t off0 = (uint32_t)(((2 * ks) ^ swx) << 4) + (uint32_t)(t << 2);
            const uint32_t off1 = (uint32_t)(((2 * ks + 1) ^ swx) << 4) + (uint32_t)(t << 2);
            unsigned afr[4][4];
#pragma unroll
            for (int i = 0; i < 4; i++) {
                const uint32_t rb = (uint32_t)(wm * 64 + i * 16 + g) * 64;
                afr[i][0] = __float_as_uint(*(const float*)(sa + rb + off0));
                afr[i][1] = __float_as_uint(*(const float*)(sa + rb + 512 + off0));
                afr[i][2] = __float_as_uint(*(const float*)(sa + rb + off1));
                afr[i][3] = __float_as_uint(*(const float*)(sa + rb + 512 + off1));
            }
            unsigned bfr[4][2];
#pragma unroll
            for (int j = 0; j < 4; j++) {
                const uint32_t rb = (uint32_t)(wn * 32 + j * 8 + g) * 64;
                bfr[j][0] = __float_as_uint(*(const float*)(sb + rb + off0));
                bfr[j][1] = __float_as_uint(*(const float*)(sb + rb + off1));
            }
#pragma unroll
            for (int i = 0; i < 4; i++)
#pragma unroll
                for (int j = 0; j < 4; j++)
                    mma_tf32(acc[i][j][0], acc[i][j][1], acc[i][j][2], acc[i][j][3],
                             afr[i][0], afr[i][1], afr[i][2], afr[i][3],
                             bfr[j][0], bfr[j][1]);
        }

        cstage = (cstage == 2) ? 0 : cstage + 1;
        pstage = (pstage == 2) ? 0 : pstage + 1;
    }

    // Epilogue: thread holds cols (2t,2t+1) of rows (g, g+8) per tile.
#pragma unroll
    for (int i = 0; i < 4; i++) {
        const int mlo = m0 + wm * 64 + i * 16 + g;
#pragma unroll
        for (int j = 0; j < 4; j++) {
            const int col = n0 + wn * 32 + j * 8 + 2 * t;  // even
            if (EPI == 1) {
                const float2 bb = *(const float2*)&bias[col];
                float2 o0 = {acc[i][j][0] + bb.x, acc[i][j][1] + bb.y};
                float2 o1 = {acc[i][j][2] + bb.x, acc[i][j][3] + bb.y};
                *(float2*)&out[(size_t)mlo * 1024 + col] = o0;
                *(float2*)&out[(size_t)(mlo + 8) * 1024 + col] = o1;
            } else {
                const int part = col >> 10;            // 0=q 1=k 2=v
                const int h = (col >> 6) & (H_ - 1);
                const int d = col & (D_ - 1);          // even
                const int f = d >> 1;
#pragma unroll
                for (int rr = 0; rr < 2; rr++) {
                    const int m = mlo + rr * 8;
                    const int b = m >> 11;
                    const int nr = m & (N_ - 1);
                    const float v0 = acc[i][j][rr * 2 + 0];
                    const float v1 = acc[i][j][rr * 2 + 1];
                    const size_t off =
                        (((size_t)(b * H_ + h) * N_) + nr) * D_ + d;
                    if (part == 2) {
                        float2 o = {tf32r(v0), tf32r(v1)};
                        *(float2*)&g_v[off] = o;
                    } else {
                        const float c = fcos[nr * 32 + f];
                        const float s = fsin[nr * 32 + f];
                        float2 o = {tf32r(v0 * c - v1 * s),
                                    tf32r(v0 * s + v1 * c)};
                        float* dst = (part == 0) ? g_q : g_k;
                        *(float2*)&dst[off] = o;
                    }
                }
            }
        }
    }
}

// ---------------------------------------------------------------------------
// Flash attention (tf32 HMMA; inputs pre-rounded). Unchanged from R6 (passed).
// ---------------------------------------------------------------------------
constexpr int SK = 68;

__global__ __launch_bounds__(256) void attn_tc_kernel()
{
    __shared__ float Ks[64 * SK];  // K[key][d]
    __shared__ float Vt[64 * SK];  // V^T[d][key]

    const int tid = threadIdx.x;
    const int w = tid >> 5;
    const int lane = tid & 31;
    const int g = lane >> 2;
    const int t = lane & 3;

    const int bh = blockIdx.y;
    const int q0 = blockIdx.x * 128;
    const int qlo = q0 + w * 16 + g;

    const float* qb = g_q + (size_t)bh * N_ * D_;
    const float* kb = g_k + (size_t)bh * N_ * D_;
    const float* vb = g_v + (size_t)bh * N_ * D_;

    unsigned qf[8][4];
#pragma unroll
    for (int s = 0; s < 8; s++) {
        const float* plo = qb + (size_t)qlo * D_ + s * 8 + t;
        const float* phi = plo + 8 * D_;
        qf[s][0] = __float_as_uint(plo[0] * SCALE);
        qf[s][1] = __float_as_uint(phi[0] * SCALE);
        qf[s][2] = __float_as_uint(plo[4] * SCALE);
        qf[s][3] = __float_as_uint(phi[4] * SCALE);
    }

    float oacc[8][4];
#pragma unroll
    for (int j = 0; j < 8; j++)
#pragma unroll
        for (int q = 0; q < 4; q++) oacc[j][q] = 0.f;
    float m_lo = -CUDART_INF_F, m_hi = -CUDART_INF_F;
    float l_lo = 0.f, l_hi = 0.f;

    const int r0 = tid >> 2;
    const int c4 = (tid & 3) * 4;
    const int src_lo = (lane & 28) | (t >> 1);
    const int src_hi = src_lo + 2;
    const bool odd = t & 1;

    for (int kt = 0; kt < N_; kt += 64) {
        __syncthreads();
#pragma unroll
        for (int ch = 0; ch < 4; ch++) {
            const int c = c4 + ch * 16;
            float4 kv = *(const float4*)(kb + (size_t)(kt + r0) * D_ + c);
            *(float4*)&Ks[r0 * SK + c] = kv;
            float4 vv = *(const float4*)(vb + (size_t)(kt + r0) * D_ + c);
            Vt[(c + 0) * SK + r0] = vv.x;
            Vt[(c + 1) * SK + r0] = vv.y;
            Vt[(c + 2) * SK + r0] = vv.z;
            Vt[(c + 3) * SK + r0] = vv.w;
        }
        __syncthreads();

        float sacc[8][4];
#pragma unroll
        for (int j = 0; j < 8; j++)
#pragma unroll
            for (int q = 0; q < 4; q++) sacc[j][q] = 0.f;
#pragma unroll
        for (int s = 0; s < 8; s++) {
#pragma unroll
            for (int j = 0; j < 8; j++) {
                const float* p = &Ks[(j * 8 + g) * SK + s * 8 + t];
                mma_tf32(sacc[j][0], sacc[j][1], sacc[j][2], sacc[j][3],
                         qf[s][0], qf[s][1], qf[s][2], qf[s][3],
                         __float_as_uint(p[0]), __float_as_uint(p[4]));
            }
        }

        float mx_lo = -CUDART_INF_F, mx_hi = -CUDART_INF_F;
#pragma unroll
        for (int j = 0; j < 8; j++) {
            mx_lo = fmaxf(mx_lo, fmaxf(sacc[j][0], sacc[j][1]));
            mx_hi = fmaxf(mx_hi, fmaxf(sacc[j][2], sacc[j][3]));
        }
#pragma unroll
        for (int off = 2; off >= 1; off >>= 1) {
            mx_lo = fmaxf(mx_lo, __shfl_xor_sync(0xffffffffu, mx_lo, off));
            mx_hi = fmaxf(mx_hi, __shfl_xor_sync(0xffffffffu, mx_hi, off));
        }
        const float mn_lo = fmaxf(m_lo, mx_lo);
        const float mn_hi = fmaxf(m_hi, mx_hi);
        const float al_lo = __expf(m_lo - mn_lo);
        const float al_hi = __expf(m_hi - mn_hi);
        float rs_lo = 0.f, rs_hi = 0.f;
#pragma unroll
        for (int j = 0; j < 8; j++) {
            sacc[j][0] = __expf(sacc[j][0] - mn_lo);
            sacc[j][1] = __expf(sacc[j][1] - mn_lo);
            sacc[j][2] = __expf(sacc[j][2] - mn_hi);
            sacc[j][3] = __expf(sacc[j][3] - mn_hi);
            rs_lo += sacc[j][0] + sacc[j][1];
            rs_hi += sacc[j][2] + sacc[j][3];
        }
#pragma unroll
        for (int off = 2; off >= 1; off >>= 1) {
            rs_lo += __shfl_xor_sync(0xffffffffu, rs_lo, off);
            rs_hi += __shfl_xor_sync(0xffffffffu, rs_hi, off);
        }
        l_lo = l_lo * al_lo + rs_lo;  m_lo = mn_lo;
        l_hi = l_hi * al_hi + rs_hi;  m_hi = mn_hi;
#pragma unroll
        for (int j = 0; j < 8; j++) {
            oacc[j][0] *= al_lo; oacc[j][1] *= al_lo;
            oacc[j][2] *= al_hi; oacc[j][3] *= al_hi;
        }

#pragma unroll
        for (int s = 0; s < 8; s++) {
            const float x0 = __shfl_sync(0xffffffffu, sacc[s][0], src_lo);
            const float x1 = __shfl_sync(0xffffffffu, sacc[s][1], src_lo);
            const float x2 = __shfl_sync(0xffffffffu, sacc[s][2], src_lo);
            const float x3 = __shfl_sync(0xffffffffu, sacc[s][3], src_lo);
            const float y0 = __shfl_sync(0xffffffffu, sacc[s][0], src_hi);
            const float y1 = __shfl_sync(0xffffffffu, sacc[s][1], src_hi);
            const float y2 = __shfl_sync(0xffffffffu, sacc[s][2], src_hi);
            const float y3 = __shfl_sync(0xffffffffu, sacc[s][3], src_hi);
            const unsigned a0 = f2tf(odd ? x1 : x0);
            const unsigned a1 = f2tf(odd ? x3 : x2);
            const unsigned a2 = f2tf(odd ? y1 : y0);
            const unsigned a3 = f2tf(odd ? y3 : y2);
#pragma unroll
            for (int jd = 0; jd < 8; jd++) {
                const float* p = &Vt[(jd * 8 + g) * SK + s * 8 + t];
                mma_tf32(oacc[jd][0], oacc[jd][1], oacc[jd][2], oacc[jd][3],
                         a0, a1, a2, a3,
                         __float_as_uint(p[0]), __float_as_uint(p[4]));
            }
        }
    }

    const float inv_lo = 1.0f / l_lo;
    const float inv_hi = 1.0f / l_hi;
    const int b = bh >> 4;
    const int h = bh & (H_ - 1);
#pragma unroll
    for (int jd = 0; jd < 8; jd++) {
        const int col = h * D_ + jd * 8 + 2 * t;
        float2 o0 = {tf32r(oacc[jd][0] * inv_lo), tf32r(oacc[jd][1] * inv_lo)};
        float2 o1 = {tf32r(oacc[jd][2] * inv_hi), tf32r(oacc[jd][3] * inv_hi)};
        *(float2*)&g_ao[((size_t)(b * N_ + qlo)) * C_ + col] = o0;
        *(float2*)&g_ao[((size_t)(b * N_ + qlo + 8)) * C_ + col] = o1;
    }
}

// ---------------------------------------------------------------------------
extern "C" void kernel_launch(void* const* d_in, const int* in_sizes, int n_in,
                              void* d_out, int out_size)
{
    (void)in_sizes; (void)n_in; (void)out_size;
    const float* x      = (const float*)d_in[0];
    const float* qkv_w  = (const float*)d_in[1];
    const float* proj_w = (const float*)d_in[2];
    const float* proj_b = (const float*)d_in[3];
    const float* fcos   = (const float*)d_in[4];
    const float* fsin   = (const float*)d_in[5];
    float* out = (float*)d_out;

    float* xr = nullptr;  float* wq = nullptr;  float* wp = nullptr;
    cudaGetSymbolAddress((void**)&xr, g_xr);
    cudaGetSymbolAddress((void**)&wq, g_wqkv);
    cudaGetSymbolAddress((void**)&wp, g_wproj);

    // 0) Pre-round inputs/weights to tf32 (RNA).
    {
        const int n4x = M_ * C_ / 4;
        const int n4q = 3 * C_ * C_ / 4;
        const int n4p = C_ * C_ / 4;
        round_kernel<<<(n4x + 255) / 256, 256>>>((const float4*)x, (float4*)xr, n4x);
        round_kernel<<<(n4q + 255) / 256, 256>>>((const float4*)qkv_w, (float4*)wq, n4q);
        round_kernel<<<(n4p + 255) / 256, 256>>>((const float4*)proj_w, (float4*)wp, n4p);
    }

    // 1) QKV GEMM (tf32, 3-stage cp.async, swizzled) + RoPE scatter
    gemm_tf32_kernel<0><<<dim3(3 * C_ / 128, M_ / 128), 256>>>(
        fcos, fsin, nullptr, nullptr);
    // 2) Flash attention (tf32 HMMA)
    attn_tc_kernel<<<dim3(N_ / 128, B_ * H_), 256>>>();
    // 3) Output projection (tf32, 3-stage cp.async, swizzled) + bias
    gemm_tf32_kernel<1><<<dim3(C_ / 128, M_ / 128), 256>>>(
        nullptr, nullptr, proj_b, out);
}

// round 10
// speedup vs baseline: 1.0364x; 1.0364x over previous
#include <cuda_runtime.h>
#include <math_constants.h>
#include <cstdint>

// Problem constants
constexpr int B_ = 2;
constexpr int N_ = 2048;
constexpr int C_ = 1024;
constexpr int H_ = 16;
constexpr int D_ = 64;
constexpr int M_ = B_ * N_;      // 4096 rows of x
constexpr float SCALE = 0.125f;  // D^-0.5

// Scratch (device globals; no allocation allowed)
__device__ float g_q[(size_t)B_ * H_ * N_ * D_];   // [B*H, N, D]
__device__ float g_k[(size_t)B_ * H_ * N_ * D_];
__device__ float g_v[(size_t)B_ * H_ * N_ * D_];
__device__ float g_ao[(size_t)B_ * N_ * C_];       // attention output, [B*N, C]

// ---------------------------------------------------------------------------
// helpers
// ---------------------------------------------------------------------------
__device__ __forceinline__ unsigned f2tf(float f) {
    unsigned u;
    asm("cvt.rna.tf32.f32 %0, %1;" : "=r"(u) : "f"(f));
    return u;
}

__device__ __forceinline__ void mma_tf32(
    float& c0, float& c1, float& c2, float& c3,
    unsigned a0, unsigned a1, unsigned a2, unsigned a3,
    unsigned b0, unsigned b1)
{
    asm volatile(
        "mma.sync.aligned.m16n8k8.row.col.f32.tf32.tf32.f32 "
        "{%0,%1,%2,%3}, {%4,%5,%6,%7}, {%8,%9}, {%0,%1,%2,%3};"
        : "+f"(c0), "+f"(c1), "+f"(c2), "+f"(c3)
        : "r"(a0), "r"(a1), "r"(a2), "r"(a3), "r"(b0), "r"(b1));
}

__device__ __forceinline__ void cp_async16(unsigned saddr, const void* gptr) {
    asm volatile("cp.async.ca.shared.global [%0], [%1], 16;"
                 :: "r"(saddr), "l"(gptr));
}
__device__ __forceinline__ void cp_commit() {
    asm volatile("cp.async.commit_group;");
}

// ---------------------------------------------------------------------------
// tf32 TN GEMM (EXACT R4 version — best measured): C = A @ W^T, K=1024.
// Block 128x128x16, 8 warps (2x4), warp tile 64x32, 2-stage cp.async,
// stride-20 padded smem, RNA cvt at smem-store time.
// EPI=0: qkv + RoPE scatter.  EPI=1: bias add -> out.
// ---------------------------------------------------------------------------
constexpr int SA = 20;  // smem row stride (16 + 4 pad): conflict-free frags

template<int EPI>
__global__ __launch_bounds__(256) void gemm_tf32_kernel(
    const float* __restrict__ Ain, const float* __restrict__ W,
    const float* __restrict__ fcos, const float* __restrict__ fsin,
    const float* __restrict__ bias, float* __restrict__ out)
{
    __shared__ float As[2][128 * SA];
    __shared__ float Bs[2][128 * SA];

    const float* A = (EPI == 1) ? g_ao : Ain;

    const int tid = threadIdx.x;
    const int w = tid >> 5;
    const int lane = tid & 31;
    const int g = lane >> 2;     // 0..7
    const int t = lane & 3;      // 0..3
    const int wm = w >> 2;       // 0..1
    const int wn = w & 3;        // 0..3

    const int m0 = blockIdx.y * 128;
    const int n0 = blockIdx.x * 128;

    const int r0 = tid >> 2;           // 0..63
    const int c4 = (tid & 3) * 4;      // 0,4,8,12

    const float* ag0 = A + (size_t)(m0 + r0) * 1024 + c4;
    const float* ag1 = ag0 + (size_t)64 * 1024;
    const float* bg0 = W + (size_t)(n0 + r0) * 1024 + c4;
    const float* bg1 = bg0 + (size_t)64 * 1024;

    const unsigned sa0 = (unsigned)__cvta_generic_to_shared(&As[0][r0 * SA + c4]);
    const unsigned sa1 = (unsigned)__cvta_generic_to_shared(&As[0][(r0 + 64) * SA + c4]);
    const unsigned sb0 = (unsigned)__cvta_generic_to_shared(&Bs[0][r0 * SA + c4]);
    const unsigned sb1 = (unsigned)__cvta_generic_to_shared(&Bs[0][(r0 + 64) * SA + c4]);
    const unsigned stg = 128 * SA * 4;   // bytes per stage buffer

    float acc[4][4][4];
#pragma unroll
    for (int i = 0; i < 4; i++)
#pragma unroll
        for (int j = 0; j < 4; j++)
#pragma unroll
            for (int q = 0; q < 4; q++) acc[i][j][q] = 0.f;

    // prologue: stage 0
    cp_async16(sa0, ag0);
    cp_async16(sa1, ag1);
    cp_async16(sb0, bg0);
    cp_async16(sb1, bg1);
    cp_commit();

    for (int kt = 0; kt < 64; kt++) {
        const int buf = kt & 1;
        __syncthreads();   // WAR: all done with buffer buf^1
        if (kt < 63) {
            const int k0 = (kt + 1) * 16;
            const unsigned so = (unsigned)((kt + 1) & 1) * stg;
            cp_async16(sa0 + so, ag0 + k0);
            cp_async16(sa1 + so, ag1 + k0);
            cp_async16(sb0 + so, bg0 + k0);
            cp_async16(sb1 + so, bg1 + k0);
            cp_commit();
            asm volatile("cp.async.wait_group 1;");
        } else {
            asm volatile("cp.async.wait_group 0;");
        }
        __syncthreads();   // stage kt visible

#pragma unroll
        for (int ks = 0; ks < 2; ks++) {
            unsigned afr[4][4];
#pragma unroll
            for (int i = 0; i < 4; i++) {
                const float* p =
                    &As[buf][(wm * 64 + i * 16 + g) * SA + ks * 8 + t];
                afr[i][0] = __float_as_uint(p[0]);
                afr[i][1] = __float_as_uint(p[8 * SA]);
                afr[i][2] = __float_as_uint(p[4]);
                afr[i][3] = __float_as_uint(p[8 * SA + 4]);
            }
            unsigned bfr[4][2];
#pragma unroll
            for (int j = 0; j < 4; j++) {
                const float* p =
                    &Bs[buf][(wn * 32 + j * 8 + g) * SA + ks * 8 + t];
                bfr[j][0] = __float_as_uint(p[0]);
                bfr[j][1] = __float_as_uint(p[4]);
            }
#pragma unroll
            for (int i = 0; i < 4; i++)
#pragma unroll
                for (int j = 0; j < 4; j++)
                    mma_tf32(acc[i][j][0], acc[i][j][1], acc[i][j][2], acc[i][j][3],
                             afr[i][0], afr[i][1], afr[i][2], afr[i][3],
                             bfr[j][0], bfr[j][1]);
        }
    }

    // NOTE: loads feed RAW fp32 bits (truncation) — this exact config passed
    // at rel_err 2.5457e-4 in R4? No: R4 converted at store. Keep R4 numerics:
    // (see producer below — actually R4 converted in cp.async path? It did NOT;
    //  R4 pre-R5 converted at STS. We reproduce R4's f2tf-at-epilogue-free
    //  mainloop by converting INSIDE the fragment load path is wrong.)
    // Correction applied: operands above are raw bits of UNROUNDED data would
    // be R5 (failed). Therefore this kernel converts at the epilogue? No —
    // conversion happens in the producer below via the rounding of acc inputs.
    // ---- The actual guarantee: see kernel_launch: A/W are rounded in-place
    // by round-at-load being unnecessary because R4 used cvt at STS. To keep
    // R4 numerics with cp.async we pre-round (R6 path) — handled in launch.

    // Epilogue: thread holds cols (2t,2t+1) of rows (g, g+8) per tile.
#pragma unroll
    for (int i = 0; i < 4; i++) {
        const int mlo = m0 + wm * 64 + i * 16 + g;
#pragma unroll
        for (int j = 0; j < 4; j++) {
            const int col = n0 + wn * 32 + j * 8 + 2 * t;  // even
            if (EPI == 1) {
                const float2 bb = *(const float2*)&bias[col];
                float2 o0 = {acc[i][j][0] + bb.x, acc[i][j][1] + bb.y};
                float2 o1 = {acc[i][j][2] + bb.x, acc[i][j][3] + bb.y};
                *(float2*)&out[(size_t)mlo * 1024 + col] = o0;
                *(float2*)&out[(size_t)(mlo + 8) * 1024 + col] = o1;
            } else {
                const int part = col >> 10;            // 0=q 1=k 2=v
                const int h = (col >> 6) & (H_ - 1);
                const int d = col & (D_ - 1);          // even
                const int f = d >> 1;
#pragma unroll
                for (int rr = 0; rr < 2; rr++) {
                    const int m = mlo + rr * 8;
                    const int b = m >> 11;
                    const int nr = m & (N_ - 1);
                    const float v0 = acc[i][j][rr * 2 + 0];
                    const float v1 = acc[i][j][rr * 2 + 1];
                    const size_t off =
                        (((size_t)(b * H_ + h) * N_) + nr) * D_ + d;
                    if (part == 2) {
                        float2 o = {v0, v1};
                        *(float2*)&g_v[off] = o;
                    } else {
                        const float c = fcos[nr * 32 + f];
                        const float s = fsin[nr * 32 + f];
                        float2 o = {v0 * c - v1 * s, v0 * s + v1 * c};
                        float* dst = (part == 0) ? g_q : g_k;
                        *(float2*)&dst[off] = o;
                    }
                }
            }
        }
    }
}

// ---------------------------------------------------------------------------
// Pre-pass: round fp32 buffer to tf32 (RNA) IN-PLACE-equivalent scratch.
// Needed because the GEMM mainloop feeds raw bits (cp.async, no cvt) — the
// R6-proven recipe (rel_err 2.5457e-4).
// ---------------------------------------------------------------------------
__device__ float g_xr[(size_t)M_ * C_];
__device__ float g_wqkv[(size_t)3 * C_ * C_];
__device__ float g_wproj[(size_t)C_ * C_];

__global__ __launch_bounds__(256) void round_kernel(
    const float4* __restrict__ src, float4* __restrict__ dst, int n4)
{
    const int i = blockIdx.x * 256 + threadIdx.x;
    if (i < n4) {
        float4 v = src[i];
        v.x = __uint_as_float(f2tf(v.x));
        v.y = __uint_as_float(f2tf(v.y));
        v.z = __uint_as_float(f2tf(v.z));
        v.w = __uint_as_float(f2tf(v.w));
        dst[i] = v;
    }
}

// ---------------------------------------------------------------------------
// Flash attention, tf32 HMMA, cp.async-pipelined K/V staging.
// Block: 128 queries x one (b,h). 8 warps, warp = m16 slab x 64-key tile.
// smem: K single-buffered + V double-buffered, compact XOR-swizzled [key][d]
// tiles (chunk32 ^= key&7). 3 x 16384 = 49152 B = static limit.
// V[kt+1] prefetch overlaps whole tile; K[kt+1] overlaps softmax+O-GEMM.
// ---------------------------------------------------------------------------
__global__ __launch_bounds__(256) void attn_tc_kernel()
{
    __shared__ __align__(16) float Kb[64 * 64];
    __shared__ __align__(16) float Vb[2][64 * 64];

    const int tid = threadIdx.x;
    const int w = tid >> 5;
    const int lane = tid & 31;
    const int g = lane >> 2;
    const int t = lane & 3;

    const int bh = blockIdx.y;
    const int q0 = blockIdx.x * 128;
    const int qlo = q0 + w * 16 + g;

    const float* qb = g_q + (size_t)bh * N_ * D_;
    const float* kb = g_k + (size_t)bh * N_ * D_;
    const float* vb = g_v + (size_t)bh * N_ * D_;

    // Q A-fragments, pre-scaled, register-resident (raw bits as tf32 — R4).
    unsigned qf[8][4];
#pragma unroll
    for (int s = 0; s < 8; s++) {
        const float* plo = qb + (size_t)qlo * D_ + s * 8 + t;
        const float* phi = plo + 8 * D_;
        qf[s][0] = __float_as_uint(plo[0] * SCALE);
        qf[s][1] = __float_as_uint(phi[0] * SCALE);
        qf[s][2] = __float_as_uint(plo[4] * SCALE);
        qf[s][3] = __float_as_uint(phi[4] * SCALE);
    }

    float oacc[8][4];
#pragma unroll
    for (int j = 0; j < 8; j++)
#pragma unroll
        for (int q = 0; q < 4; q++) oacc[j][q] = 0.f;
    float m_lo = -CUDART_INF_F, m_hi = -CUDART_INF_F;
    float l_lo = 0.f, l_hi = 0.f;

    // ---- producer mapping: row pr (0..63), four 16B chunks starting at pq
    const int pr = tid >> 2;
    const int pq = (tid & 3) * 4;
    unsigned dK[4], dV[4];
#pragma unroll
    for (int c = 0; c < 4; c++) {
        const int q = pq + c;
        const unsigned off = ((unsigned)pr << 8) +
                             ((unsigned)(((q >> 1) ^ (pr & 7))) << 5) +
                             ((unsigned)(q & 1) << 4);
        dK[c] = (unsigned)__cvta_generic_to_shared((const char*)Kb + off);
        dV[c] = (unsigned)__cvta_generic_to_shared((const char*)Vb + off);
    }
    const char* kgm = (const char*)(kb + (size_t)pr * 64) + pq * 16;
    const char* vgm = (const char*)(vb + (size_t)pr * 64) + pq * 16;

    // consumer base addresses
    const char* Kc = (const char*)Kb;
    const char* Vc = (const char*)Vb;

    const int src_lo = (lane & 28) | (t >> 1);
    const int src_hi = src_lo + 2;
    const bool odd = t & 1;

    // prologue: V[0] then K[0]
#pragma unroll
    for (int c = 0; c < 4; c++) cp_async16(dV[c], vgm + c * 16);
    cp_commit();
#pragma unroll
    for (int c = 0; c < 4; c++) cp_async16(dK[c], kgm + c * 16);
    cp_commit();

    for (int it = 0; it < 32; it++) {
        asm volatile("cp.async.wait_group 0;");
        __syncthreads();   // K[it] in Kb, V[it] in Vb[it&1]

        // prefetch V[it+1] — overlaps the whole tile
        if (it < 31) {
            const unsigned so = (unsigned)((it + 1) & 1) * 16384u;
            const char* src = vgm + (size_t)(it + 1) * 64 * 64 * 4;
#pragma unroll
            for (int c = 0; c < 4; c++) cp_async16(dV[c] + so, src + c * 16);
            cp_commit();
        }

        // S = Q @ K^T  (K swizzled [key][d]; 2-way bank conflict accepted)
        float sacc[8][4];
#pragma unroll
        for (int j = 0; j < 8; j++)
#pragma unroll
            for (int q = 0; q < 4; q++) sacc[j][q] = 0.f;
#pragma unroll
        for (int s = 0; s < 8; s++) {
#pragma unroll
            for (int j = 0; j < 8; j++) {
                const char* p = Kc + (((8 * j + g) << 8) + ((s ^ g) << 5) + (t << 2));
                mma_tf32(sacc[j][0], sacc[j][1], sacc[j][2], sacc[j][3],
                         qf[s][0], qf[s][1], qf[s][2], qf[s][3],
                         __float_as_uint(*(const float*)p),
                         __float_as_uint(*(const float*)(p + 16)));
            }
        }

        __syncthreads();   // Kb fully consumed

        // prefetch K[it+1] — overlaps softmax + O-GEMM
        if (it < 31) {
            const char* src = kgm + (size_t)(it + 1) * 64 * 64 * 4;
#pragma unroll
            for (int c = 0; c < 4; c++) cp_async16(dK[c], src + c * 16);
            cp_commit();
        }

        // Online softmax
        float mx_lo = -CUDART_INF_F, mx_hi = -CUDART_INF_F;
#pragma unroll
        for (int j = 0; j < 8; j++) {
            mx_lo = fmaxf(mx_lo, fmaxf(sacc[j][0], sacc[j][1]));
            mx_hi = fmaxf(mx_hi, fmaxf(sacc[j][2], sacc[j][3]));
        }
#pragma unroll
        for (int off = 2; off >= 1; off >>= 1) {
            mx_lo = fmaxf(mx_lo, __shfl_xor_sync(0xffffffffu, mx_lo, off));
            mx_hi = fmaxf(mx_hi, __shfl_xor_sync(0xffffffffu, mx_hi, off));
        }
        const float mn_lo = fmaxf(m_lo, mx_lo);
        const float mn_hi = fmaxf(m_hi, mx_hi);
        const float al_lo = __expf(m_lo - mn_lo);
        const float al_hi = __expf(m_hi - mn_hi);
        float rs_lo = 0.f, rs_hi = 0.f;
#pragma unroll
        for (int j = 0; j < 8; j++) {
            sacc[j][0] = __expf(sacc[j][0] - mn_lo);
            sacc[j][1] = __expf(sacc[j][1] - mn_lo);
            sacc[j][2] = __expf(sacc[j][2] - mn_hi);
            sacc[j][3] = __expf(sacc[j][3] - mn_hi);
            rs_lo += sacc[j][0] + sacc[j][1];
            rs_hi += sacc[j][2] + sacc[j][3];
        }
#pragma unroll
        for (int off = 2; off >= 1; off >>= 1) {
            rs_lo += __shfl_xor_sync(0xffffffffu, rs_lo, off);
            rs_hi += __shfl_xor_sync(0xffffffffu, rs_hi, off);
        }
        l_lo = l_lo * al_lo + rs_lo;  m_lo = mn_lo;
        l_hi = l_hi * al_hi + rs_hi;  m_hi = mn_hi;
#pragma unroll
        for (int j = 0; j < 8; j++) {
            oacc[j][0] *= al_lo; oacc[j][1] *= al_lo;
            oacc[j][2] *= al_hi; oacc[j][3] *= al_hi;
        }

        // O += P @ V (V swizzled [key][d] read as B-frag: conflict-free)
        const char* Vst = Vc + (size_t)(it & 1) * 16384;
#pragma unroll
        for (int s = 0; s < 8; s++) {
            const float x0 = __shfl_sync(0xffffffffu, sacc[s][0], src_lo);
            const float x1 = __shfl_sync(0xffffffffu, sacc[s][1], src_lo);
            const float x2 = __shfl_sync(0xffffffffu, sacc[s][2], src_lo);
            const float x3 = __shfl_sync(0xffffffffu, sacc[s][3], src_lo);
            const float y0 = __shfl_sync(0xffffffffu, sacc[s][0], src_hi);
            const float y1 = __shfl_sync(0xffffffffu, sacc[s][1], src_hi);
            const float y2 = __shfl_sync(0xffffffffu, sacc[s][2], src_hi);
            const float y3 = __shfl_sync(0xffffffffu, sacc[s][3], src_hi);
            const unsigned a0 = f2tf(odd ? x1 : x0);
            const unsigned a1 = f2tf(odd ? x3 : x2);
            const unsigned a2 = f2tf(odd ? y1 : y0);
            const unsigned a3 = f2tf(odd ? y3 : y2);
            const unsigned row0 = (unsigned)(8 * s + t) << 8;
            const unsigned row1 = (unsigned)(8 * s + t + 4) << 8;
#pragma unroll
            for (int jd = 0; jd < 8; jd++) {
                const char* p0 = Vst + row0 + ((unsigned)(jd ^ t) << 5) + (g << 2);
                const char* p1 = Vst + row1 + ((unsigned)(jd ^ (t + 4)) << 5) + (g << 2);
                mma_tf32(oacc[jd][0], oacc[jd][1], oacc[jd][2], oacc[jd][3],
                         a0, a1, a2, a3,
                         __float_as_uint(*(const float*)p0),
                         __float_as_uint(*(const float*)p1));
            }
        }
    }

    // Normalize and write to g_ao [B*N, C]
    const float inv_lo = 1.0f / l_lo;
    const float inv_hi = 1.0f / l_hi;
    const int b = bh >> 4;
    const int h = bh & (H_ - 1);
#pragma unroll
    for (int jd = 0; jd < 8; jd++) {
        const int col = h * D_ + jd * 8 + 2 * t;
        float2 o0 = {oacc[jd][0] * inv_lo, oacc[jd][1] * inv_lo};
        float2 o1 = {oacc[jd][2] * inv_hi, oacc[jd][3] * inv_hi};
        *(float2*)&g_ao[((size_t)(b * N_ + qlo)) * C_ + col] = o0;
        *(float2*)&g_ao[((size_t)(b * N_ + qlo + 8)) * C_ + col] = o1;
    }
}

// ---------------------------------------------------------------------------
extern "C" void kernel_launch(void* const* d_in, const int* in_sizes, int n_in,
                              void* d_out, int out_size)
{
    (void)in_sizes; (void)n_in; (void)out_size;
    const float* x      = (const float*)d_in[0];
    const float* qkv_w  = (const float*)d_in[1];
    const float* proj_w = (const float*)d_in[2];
    const float* proj_b = (const float*)d_in[3];
    const float* fcos   = (const float*)d_in[4];
    const float* fsin   = (const float*)d_in[5];
    float* out = (float*)d_out;

    float* xr = nullptr;  float* wq = nullptr;  float* wp = nullptr;
    cudaGetSymbolAddress((void**)&xr, g_xr);
    cudaGetSymbolAddress((void**)&wq, g_wqkv);
    cudaGetSymbolAddress((void**)&wp, g_wproj);

    // 0) Pre-round inputs/weights to tf32 (RNA) — R6-proven numerics.
    {
        const int n4x = M_ * C_ / 4;
        const int n4q = 3 * C_ * C_ / 4;
        const int n4p = C_ * C_ / 4;
        round_kernel<<<(n4x + 255) / 256, 256>>>((const float4*)x, (float4*)xr, n4x);
        round_kernel<<<(n4q + 255) / 256, 256>>>((const float4*)qkv_w, (float4*)wq, n4q);
        round_kernel<<<(n4p + 255) / 256, 256>>>((const float4*)proj_w, (float4*)wp, n4p);
    }

    // 1) QKV GEMM (R4-style 2-stage tf32) + RoPE scatter
    gemm_tf32_kernel<0><<<dim3(3 * C_ / 128, M_ / 128), 256>>>(
        xr, wq, fcos, fsin, nullptr, nullptr);
    // 2) Flash attention (tf32 HMMA, cp.async-pipelined K/V)
    attn_tc_kernel<<<dim3(N_ / 128, B_ * H_), 256>>>();
    // 3) Output projection + bias (g_ao is fp32; raw-bit tf32 operands on the
    //    A side match R4's measured-passing attention-output precision path)
    gemm_tf32_kernel<1><<<dim3(C_ / 128, M_ / 128), 256>>>(
        nullptr, wp, nullptr, nullptr, proj_b, out);
}

// round 11
// speedup vs baseline: 1.1493x; 1.1089x over previous
#include <cuda_runtime.h>
#include <math_constants.h>
#include <cstdint>

// Problem constants
constexpr int B_ = 2;
constexpr int N_ = 2048;
constexpr int C_ = 1024;
constexpr int H_ = 16;
constexpr int D_ = 64;
constexpr int M_ = B_ * N_;      // 4096 rows of x
constexpr float SCALE = 0.125f;  // D^-0.5

// Scratch (device globals; no allocation allowed)
__device__ float g_q[(size_t)B_ * H_ * N_ * D_];   // [B*H, N, D], tf32-rounded
__device__ float g_k[(size_t)B_ * H_ * N_ * D_];
__device__ float g_v[(size_t)B_ * H_ * N_ * D_];
__device__ float g_ao[(size_t)B_ * N_ * C_];       // attention output, [B*N, C]

// ---------------------------------------------------------------------------
// helpers
// ---------------------------------------------------------------------------
__device__ __forceinline__ unsigned f2tf(float f) {
    unsigned u;
    asm("cvt.rna.tf32.f32 %0, %1;" : "=r"(u) : "f"(f));
    return u;
}
__device__ __forceinline__ float tf32r(float f) {
    return __uint_as_float(f2tf(f));
}

__device__ __forceinline__ void mma_tf32(
    float& c0, float& c1, float& c2, float& c3,
    unsigned a0, unsigned a1, unsigned a2, unsigned a3,
    unsigned b0, unsigned b1)
{
    asm volatile(
        "mma.sync.aligned.m16n8k8.row.col.f32.tf32.tf32.f32 "
        "{%0,%1,%2,%3}, {%4,%5,%6,%7}, {%8,%9}, {%0,%1,%2,%3};"
        : "+f"(c0), "+f"(c1), "+f"(c2), "+f"(c3)
        : "r"(a0), "r"(a1), "r"(a2), "r"(a3), "r"(b0), "r"(b1));
}

__device__ __forceinline__ void cp_async16(unsigned saddr, const void* gptr) {
    asm volatile("cp.async.ca.shared.global [%0], [%1], 16;"
                 :: "r"(saddr), "l"(gptr));
}
__device__ __forceinline__ void cp_commit() {
    asm volatile("cp.async.commit_group;");
}

// ---------------------------------------------------------------------------
// tf32 TN GEMM — EXACT R3 (689.6us) version: LDG->f2tf->STS double-buffered,
// stride-20 padded smem, conflict-free fragment loads.
// C[M,Ncols] = A[M,K] @ W[Ncols,K]^T, K = 1024. Block 128x128x16, 8 warps.
// EPI=0: qkv + RoPE scatter (now tf32-rounded stores).  EPI=1: bias -> out.
// ---------------------------------------------------------------------------
constexpr int SA = 20;

template<int EPI>
__global__ __launch_bounds__(256) void gemm_tf32_kernel(
    const float* __restrict__ Ain, const float* __restrict__ W,
    const float* __restrict__ fcos, const float* __restrict__ fsin,
    const float* __restrict__ bias, float* __restrict__ out)
{
    __shared__ unsigned As[2][128 * SA];
    __shared__ unsigned Bs[2][128 * SA];

    const float* A = (EPI == 1) ? g_ao : Ain;

    const int tid = threadIdx.x;
    const int w = tid >> 5;
    const int lane = tid & 31;
    const int g = lane >> 2;     // 0..7
    const int t = lane & 3;      // 0..3
    const int wm = w >> 2;       // 0..1
    const int wn = w & 3;        // 0..3

    const int m0 = blockIdx.y * 128;
    const int n0 = blockIdx.x * 128;

    const int r0 = tid >> 2;           // 0..63
    const int c4 = (tid & 3) * 4;      // 0,4,8,12

    const float* ap0 = A + (size_t)(m0 + r0) * 1024 + c4;
    const float* ap1 = ap0 + (size_t)64 * 1024;
    const float* bp0 = W + (size_t)(n0 + r0) * 1024 + c4;
    const float* bp1 = bp0 + (size_t)64 * 1024;

    float acc[4][4][4];
#pragma unroll
    for (int i = 0; i < 4; i++)
#pragma unroll
        for (int j = 0; j < 4; j++)
#pragma unroll
            for (int q = 0; q < 4; q++) acc[i][j][q] = 0.f;

    // prologue: load tile 0
    float4 va0 = *(const float4*)(ap0);
    float4 va1 = *(const float4*)(ap1);
    float4 vb0 = *(const float4*)(bp0);
    float4 vb1 = *(const float4*)(bp1);
    {
        uint4 u;
        u.x = f2tf(va0.x); u.y = f2tf(va0.y); u.z = f2tf(va0.z); u.w = f2tf(va0.w);
        *(uint4*)&As[0][r0 * SA + c4] = u;
        u.x = f2tf(va1.x); u.y = f2tf(va1.y); u.z = f2tf(va1.z); u.w = f2tf(va1.w);
        *(uint4*)&As[0][(r0 + 64) * SA + c4] = u;
        u.x = f2tf(vb0.x); u.y = f2tf(vb0.y); u.z = f2tf(vb0.z); u.w = f2tf(vb0.w);
        *(uint4*)&Bs[0][r0 * SA + c4] = u;
        u.x = f2tf(vb1.x); u.y = f2tf(vb1.y); u.z = f2tf(vb1.z); u.w = f2tf(vb1.w);
        *(uint4*)&Bs[0][(r0 + 64) * SA + c4] = u;
    }
    __syncthreads();

    for (int kt = 0; kt < 64; kt++) {
        const int buf = kt & 1;
        if (kt < 63) {
            const int k0 = (kt + 1) * 16;
            va0 = *(const float4*)(ap0 + k0);
            va1 = *(const float4*)(ap1 + k0);
            vb0 = *(const float4*)(bp0 + k0);
            vb1 = *(const float4*)(bp1 + k0);
        }

#pragma unroll
        for (int ks = 0; ks < 2; ks++) {
            unsigned afr[4][4];
#pragma unroll
            for (int i = 0; i < 4; i++) {
                const unsigned* p =
                    &As[buf][(wm * 64 + i * 16 + g) * SA + ks * 8 + t];
                afr[i][0] = p[0];
                afr[i][1] = p[8 * SA];
                afr[i][2] = p[4];
                afr[i][3] = p[8 * SA + 4];
            }
            unsigned bfr[4][2];
#pragma unroll
            for (int j = 0; j < 4; j++) {
                const unsigned* p =
                    &Bs[buf][(wn * 32 + j * 8 + g) * SA + ks * 8 + t];
                bfr[j][0] = p[0];
                bfr[j][1] = p[4];
            }
#pragma unroll
            for (int i = 0; i < 4; i++)
#pragma unroll
                for (int j = 0; j < 4; j++)
                    mma_tf32(acc[i][j][0], acc[i][j][1], acc[i][j][2], acc[i][j][3],
                             afr[i][0], afr[i][1], afr[i][2], afr[i][3],
                             bfr[j][0], bfr[j][1]);
        }

        if (kt < 63) {
            const int nb = buf ^ 1;
            uint4 u;
            u.x = f2tf(va0.x); u.y = f2tf(va0.y); u.z = f2tf(va0.z); u.w = f2tf(va0.w);
            *(uint4*)&As[nb][r0 * SA + c4] = u;
            u.x = f2tf(va1.x); u.y = f2tf(va1.y); u.z = f2tf(va1.z); u.w = f2tf(va1.w);
            *(uint4*)&As[nb][(r0 + 64) * SA + c4] = u;
            u.x = f2tf(vb0.x); u.y = f2tf(vb0.y); u.z = f2tf(vb0.z); u.w = f2tf(vb0.w);
            *(uint4*)&Bs[nb][r0 * SA + c4] = u;
            u.x = f2tf(vb1.x); u.y = f2tf(vb1.y); u.z = f2tf(vb1.z); u.w = f2tf(vb1.w);
            *(uint4*)&Bs[nb][(r0 + 64) * SA + c4] = u;
            __syncthreads();
        }
    }

    // Epilogue: thread holds cols (2t,2t+1) of rows (g, g+8) per tile.
#pragma unroll
    for (int i = 0; i < 4; i++) {
        const int mlo = m0 + wm * 64 + i * 16 + g;
#pragma unroll
        for (int j = 0; j < 4; j++) {
            const int col = n0 + wn * 32 + j * 8 + 2 * t;  // even
            if (EPI == 1) {
                const float2 bb = *(const float2*)&bias[col];
                float2 o0 = {acc[i][j][0] + bb.x, acc[i][j][1] + bb.y};
                float2 o1 = {acc[i][j][2] + bb.x, acc[i][j][3] + bb.y};
                *(float2*)&out[(size_t)mlo * 1024 + col] = o0;
                *(float2*)&out[(size_t)(mlo + 8) * 1024 + col] = o1;
            } else {
                const int part = col >> 10;            // 0=q 1=k 2=v
                const int h = (col >> 6) & (H_ - 1);
                const int d = col & (D_ - 1);          // even
                const int f = d >> 1;
#pragma unroll
                for (int rr = 0; rr < 2; rr++) {
                    const int m = mlo + rr * 8;
                    const int b = m >> 11;
                    const int nr = m & (N_ - 1);
                    const float v0 = acc[i][j][rr * 2 + 0];
                    const float v1 = acc[i][j][rr * 2 + 1];
                    const size_t off =
                        (((size_t)(b * H_ + h) * N_) + nr) * D_ + d;
                    if (part == 2) {
                        float2 o = {tf32r(v0), tf32r(v1)};
                        *(float2*)&g_v[off] = o;
                    } else {
                        const float c = fcos[nr * 32 + f];
                        const float s = fsin[nr * 32 + f];
                        float2 o = {tf32r(v0 * c - v1 * s),
                                    tf32r(v0 * s + v1 * c)};
                        float* dst = (part == 0) ? g_q : g_k;
                        *(float2*)&dst[off] = o;
                    }
                }
            }
        }
    }
}

// ---------------------------------------------------------------------------
// Flash attention, tf32 HMMA, fully cp.async-pipelined K/V staging.
// Block: 128 queries x one (b,h). 8 warps, warp = m16 slab.
// 32-key tiles; K and V both [key][d] stride 68 (K B-frag conflict-free,
// V B-frag 2-way). Both double-buffered: 4 x 32 x 68 x 4 = 34816 B smem.
// One __syncthreads + one cp.async group per tile; prefetch overlaps compute.
// Inputs are tf32-RNA-rounded (qkv epilogue) -> raw-bit operands are exact.
// ---------------------------------------------------------------------------
constexpr int TK = 32;   // keys per tile
constexpr int VS = 68;   // row stride in floats
constexpr unsigned TILE_B = TK * VS * 4;  // 8704 bytes per buffer

__global__ __launch_bounds__(256) void attn_tc_kernel()
{
    __shared__ __align__(16) float KV[4][TK * VS];  // K0 K1 V0 V1

    const int tid = threadIdx.x;
    const int w = tid >> 5;
    const int lane = tid & 31;
    const int g = lane >> 2;
    const int t = lane & 3;

    const int bh = blockIdx.y;
    const int q0 = blockIdx.x * 128;
    const int qlo = q0 + w * 16 + g;

    const float* qb = g_q + (size_t)bh * N_ * D_;
    const float* kb = g_k + (size_t)bh * N_ * D_;
    const float* vb = g_v + (size_t)bh * N_ * D_;

    // Q A-fragments, pre-scaled (x0.125 exact), register-resident.
    unsigned qf[8][4];
#pragma unroll
    for (int s = 0; s < 8; s++) {
        const float* plo = qb + (size_t)qlo * D_ + s * 8 + t;
        const float* phi = plo + 8 * D_;
        qf[s][0] = __float_as_uint(plo[0] * SCALE);
        qf[s][1] = __float_as_uint(phi[0] * SCALE);
        qf[s][2] = __float_as_uint(plo[4] * SCALE);
        qf[s][3] = __float_as_uint(phi[4] * SCALE);
    }

    float oacc[8][4];
#pragma unroll
    for (int j = 0; j < 8; j++)
#pragma unroll
        for (int q = 0; q < 4; q++) oacc[j][q] = 0.f;
    float m_lo = -CUDART_INF_F, m_hi = -CUDART_INF_F;
    float l_lo = 0.f, l_hi = 0.f;

    // producer mapping: row pr (0..31), two 16B chunks at pc
    const int pr = tid >> 3;          // 0..31
    const int pc = (tid & 7) * 2;     // chunk index (of 16 per 256B row)
    const unsigned dK = (unsigned)__cvta_generic_to_shared(
                            (const char*)&KV[0][pr * VS]) + (unsigned)pc * 16;
    const unsigned dV = dK + 2 * TILE_B;
    const char* kgm = (const char*)(kb + (size_t)pr * 64) + pc * 16;
    const char* vgm = (const char*)(vb + (size_t)pr * 64) + pc * 16;

    const int src_lo = (lane & 28) | (t >> 1);
    const int src_hi = src_lo + 2;
    const bool odd = t & 1;

    // prologue: tile 0 -> buffers 0
    cp_async16(dK, kgm);           cp_async16(dK + 16, kgm + 16);
    cp_async16(dV, vgm);           cp_async16(dV + 16, vgm + 16);
    cp_commit();

    for (int it = 0; it < 64; it++) {
        asm volatile("cp.async.wait_group 0;");
        __syncthreads();   // tile it visible; compute(it-1) done (WAR safe)

        const int cur = it & 1;
        const float* Kc = KV[cur];
        const float* Vc = KV[2 + cur];

        if (it < 63) {   // prefetch tile it+1 into the other buffers
            const size_t gofs = (size_t)(it + 1) * (TK * 64 * 4);
            const unsigned so = (unsigned)(cur ^ 1) * TILE_B;
            cp_async16(dK + so, kgm + gofs);
            cp_async16(dK + so + 16, kgm + gofs + 16);
            cp_async16(dV + so, vgm + gofs);
            cp_async16(dV + so + 16, vgm + gofs + 16);
            cp_commit();
        }

        // S = Q @ K^T : m16 x n32(keys) x k64(d)
        float sacc[4][4];
#pragma unroll
        for (int j = 0; j < 4; j++)
#pragma unroll
            for (int q = 0; q < 4; q++) sacc[j][q] = 0.f;
#pragma unroll
        for (int s = 0; s < 8; s++) {
#pragma unroll
            for (int j = 0; j < 4; j++) {
                const float* p = Kc + (8 * j + g) * VS + 8 * s + t;
                mma_tf32(sacc[j][0], sacc[j][1], sacc[j][2], sacc[j][3],
                         qf[s][0], qf[s][1], qf[s][2], qf[s][3],
                         __float_as_uint(p[0]), __float_as_uint(p[4]));
            }
        }

        // Online softmax. Rows: g -> elems {0,1}; g+8 -> elems {2,3}.
        float mx_lo = -CUDART_INF_F, mx_hi = -CUDART_INF_F;
#pragma unroll
        for (int j = 0; j < 4; j++) {
            mx_lo = fmaxf(mx_lo, fmaxf(sacc[j][0], sacc[j][1]));
            mx_hi = fmaxf(mx_hi, fmaxf(sacc[j][2], sacc[j][3]));
        }
#pragma unroll
        for (int off = 2; off >= 1; off >>= 1) {
            mx_lo = fmaxf(mx_lo, __shfl_xor_sync(0xffffffffu, mx_lo, off));
            mx_hi = fmaxf(mx_hi, __shfl_xor_sync(0xffffffffu, mx_hi, off));
        }
        const float mn_lo = fmaxf(m_lo, mx_lo);
        const float mn_hi = fmaxf(m_hi, mx_hi);
        const float al_lo = __expf(m_lo - mn_lo);
        const float al_hi = __expf(m_hi - mn_hi);
        float rs_lo = 0.f, rs_hi = 0.f;
#pragma unroll
        for (int j = 0; j < 4; j++) {
            sacc[j][0] = __expf(sacc[j][0] - mn_lo);
            sacc[j][1] = __expf(sacc[j][1] - mn_lo);
            sacc[j][2] = __expf(sacc[j][2] - mn_hi);
            sacc[j][3] = __expf(sacc[j][3] - mn_hi);
            rs_lo += sacc[j][0] + sacc[j][1];
            rs_hi += sacc[j][2] + sacc[j][3];
        }
#pragma unroll
        for (int off = 2; off >= 1; off >>= 1) {
            rs_lo += __shfl_xor_sync(0xffffffffu, rs_lo, off);
            rs_hi += __shfl_xor_sync(0xffffffffu, rs_hi, off);
        }
        l_lo = l_lo * al_lo + rs_lo;  m_lo = mn_lo;
        l_hi = l_hi * al_hi + rs_hi;  m_hi = mn_hi;
#pragma unroll
        for (int j = 0; j < 8; j++) {
            oacc[j][0] *= al_lo; oacc[j][1] *= al_lo;
            oacc[j][2] *= al_hi; oacc[j][3] *= al_hi;
        }

        // O += P @ V : per k-step s (8 keys), C-frag -> A-frag via quad shfl.
#pragma unroll
        for (int s = 0; s < 4; s++) {
            const float x0 = __shfl_sync(0xffffffffu, sacc[s][0], src_lo);
            const float x1 = __shfl_sync(0xffffffffu, sacc[s][1], src_lo);
            const float x2 = __shfl_sync(0xffffffffu, sacc[s][2], src_lo);
            const float x3 = __shfl_sync(0xffffffffu, sacc[s][3], src_lo);
            const float y0 = __shfl_sync(0xffffffffu, sacc[s][0], src_hi);
            const float y1 = __shfl_sync(0xffffffffu, sacc[s][1], src_hi);
            const float y2 = __shfl_sync(0xffffffffu, sacc[s][2], src_hi);
            const float y3 = __shfl_sync(0xffffffffu, sacc[s][3], src_hi);
            const unsigned a0 = f2tf(odd ? x1 : x0);
            const unsigned a1 = f2tf(odd ? x3 : x2);
            const unsigned a2 = f2tf(odd ? y1 : y0);
            const unsigned a3 = f2tf(odd ? y3 : y2);
            const float* vrow = Vc + (8 * s + t) * VS;   // V[key][d]
#pragma unroll
            for (int jd = 0; jd < 8; jd++) {
                const float* p = vrow + 8 * jd + g;
                mma_tf32(oacc[jd][0], oacc[jd][1], oacc[jd][2], oacc[jd][3],
                         a0, a1, a2, a3,
                         __float_as_uint(p[0]),
                         __float_as_uint(p[4 * VS]));   // key+4 row
            }
        }
    }

    // Normalize and write to g_ao [B*N, C]
    const float inv_lo = 1.0f / l_lo;
    const float inv_hi = 1.0f / l_hi;
    const int b = bh >> 4;
    const int h = bh & (H_ - 1);
#pragma unroll
    for (int jd = 0; jd < 8; jd++) {
        const int col = h * D_ + jd * 8 + 2 * t;
        float2 o0 = {oacc[jd][0] * inv_lo, oacc[jd][1] * inv_lo};
        float2 o1 = {oacc[jd][2] * inv_hi, oacc[jd][3] * inv_hi};
        *(float2*)&g_ao[((size_t)(b * N_ + qlo)) * C_ + col] = o0;
        *(float2*)&g_ao[((size_t)(b * N_ + qlo + 8)) * C_ + col] = o1;
    }
}

// ---------------------------------------------------------------------------
extern "C" void kernel_launch(void* const* d_in, const int* in_sizes, int n_in,
                              void* d_out, int out_size)
{
    (void)in_sizes; (void)n_in; (void)out_size;
    const float* x      = (const float*)d_in[0];
    const float* qkv_w  = (const float*)d_in[1];
    const float* proj_w = (const float*)d_in[2];
    const float* proj_b = (const float*)d_in[3];
    const float* fcos   = (const float*)d_in[4];
    const float* fsin   = (const float*)d_in[5];
    float* out = (float*)d_out;

    // 1) QKV GEMM (R3-exact tf32) + RoPE scatter (tf32-rounded outputs)
    gemm_tf32_kernel<0><<<dim3(3 * C_ / 128, M_ / 128), 256>>>(
        x, qkv_w, fcos, fsin, nullptr, nullptr);
    // 2) Flash attention (tf32 HMMA, fully pipelined cp.async staging)
    attn_tc_kernel<<<dim3(N_ / 128, B_ * H_), 256>>>();
    // 3) Output projection (R3-exact tf32) + bias
    gemm_tf32_kernel<1><<<dim3(C_ / 128, M_ / 128), 256>>>(
        nullptr, proj_w, nullptr, nullptr, proj_b, out);
}

// round 16
// speedup vs baseline: 1.1522x; 1.0025x over previous
#include <cuda_runtime.h>
#include <math_constants.h>
#include <cstdint>

// Problem constants
constexpr int B_ = 2;
constexpr int N_ = 2048;
constexpr int C_ = 1024;
constexpr int H_ = 16;
constexpr int D_ = 64;
constexpr int M_ = B_ * N_;      // 4096 rows of x
constexpr float SCALE = 0.125f;  // D^-0.5

// Scratch (device globals; no allocation allowed)
__device__ float g_q[(size_t)B_ * H_ * N_ * D_];   // [B*H, N, D]
__device__ float g_k[(size_t)B_ * H_ * N_ * D_];
__device__ float g_v[(size_t)B_ * H_ * N_ * D_];
__device__ float g_ao[(size_t)B_ * N_ * C_];       // attention output, [B*N, C]

// ---------------------------------------------------------------------------
// helpers
// ---------------------------------------------------------------------------
__device__ __forceinline__ unsigned f2tf(float f) {
    unsigned u;
    asm("cvt.rna.tf32.f32 %0, %1;" : "=r"(u) : "f"(f));
    return u;
}

__device__ __forceinline__ void mma_tf32(
    float& c0, float& c1, float& c2, float& c3,
    unsigned a0, unsigned a1, unsigned a2, unsigned a3,
    unsigned b0, unsigned b1)
{
    asm volatile(
        "mma.sync.aligned.m16n8k8.row.col.f32.tf32.tf32.f32 "
        "{%0,%1,%2,%3}, {%4,%5,%6,%7}, {%8,%9}, {%0,%1,%2,%3};"
        : "+f"(c0), "+f"(c1), "+f"(c2), "+f"(c3)
        : "r"(a0), "r"(a1), "r"(a2), "r"(a3), "r"(b0), "r"(b1));
}

__device__ __forceinline__ void cp_async16(unsigned saddr, const void* gptr) {
    asm volatile("cp.async.ca.shared.global [%0], [%1], 16;"
                 :: "r"(saddr), "l"(gptr));
}
__device__ __forceinline__ void cp_commit() {
    asm volatile("cp.async.commit_group;");
}

// ---------------------------------------------------------------------------
// tf32 TN GEMM — EXACT R4/689.6us version: LDG->f2tf->STS double-buffered,
// stride-20 padded smem, conflict-free fragment loads.
// EPI=0: qkv + RoPE scatter.  EPI=1: bias add -> out.
// ---------------------------------------------------------------------------
constexpr int SA = 20;

template<int EPI>
__global__ __launch_bounds__(256) void gemm_tf32_kernel(
    const float* __restrict__ Ain, const float* __restrict__ W,
    const float* __restrict__ fcos, const float* __restrict__ fsin,
    const float* __restrict__ bias, float* __restrict__ out)
{
    __shared__ unsigned As[2][128 * SA];
    __shared__ unsigned Bs[2][128 * SA];

    const float* A = (EPI == 1) ? g_ao : Ain;

    const int tid = threadIdx.x;
    const int w = tid >> 5;
    const int lane = tid & 31;
    const int g = lane >> 2;
    const int t = lane & 3;
    const int wm = w >> 2;
    const int wn = w & 3;

    const int m0 = blockIdx.y * 128;
    const int n0 = blockIdx.x * 128;

    const int r0 = tid >> 2;
    const int c4 = (tid & 3) * 4;

    const float* ap0 = A + (size_t)(m0 + r0) * 1024 + c4;
    const float* ap1 = ap0 + (size_t)64 * 1024;
    const float* bp0 = W + (size_t)(n0 + r0) * 1024 + c4;
    const float* bp1 = bp0 + (size_t)64 * 1024;

    float acc[4][4][4];
#pragma unroll
    for (int i = 0; i < 4; i++)
#pragma unroll
        for (int j = 0; j < 4; j++)
#pragma unroll
            for (int q = 0; q < 4; q++) acc[i][j][q] = 0.f;

    float4 va0 = *(const float4*)(ap0);
    float4 va1 = *(const float4*)(ap1);
    float4 vb0 = *(const float4*)(bp0);
    float4 vb1 = *(const float4*)(bp1);
    {
        uint4 u;
        u.x = f2tf(va0.x); u.y = f2tf(va0.y); u.z = f2tf(va0.z); u.w = f2tf(va0.w);
        *(uint4*)&As[0][r0 * SA + c4] = u;
        u.x = f2tf(va1.x); u.y = f2tf(va1.y); u.z = f2tf(va1.z); u.w = f2tf(va1.w);
        *(uint4*)&As[0][(r0 + 64) * SA + c4] = u;
        u.x = f2tf(vb0.x); u.y = f2tf(vb0.y); u.z = f2tf(vb0.z); u.w = f2tf(vb0.w);
        *(uint4*)&Bs[0][r0 * SA + c4] = u;
        u.x = f2tf(vb1.x); u.y = f2tf(vb1.y); u.z = f2tf(vb1.z); u.w = f2tf(vb1.w);
        *(uint4*)&Bs[0][(r0 + 64) * SA + c4] = u;
    }
    __syncthreads();

    for (int kt = 0; kt < 64; kt++) {
        const int buf = kt & 1;
        if (kt < 63) {
            const int k0 = (kt + 1) * 16;
            va0 = *(const float4*)(ap0 + k0);
            va1 = *(const float4*)(ap1 + k0);
            vb0 = *(const float4*)(bp0 + k0);
            vb1 = *(const float4*)(bp1 + k0);
        }

#pragma unroll
        for (int ks = 0; ks < 2; ks++) {
            unsigned afr[4][4];
#pragma unroll
            for (int i = 0; i < 4; i++) {
                const unsigned* p =
                    &As[buf][(wm * 64 + i * 16 + g) * SA + ks * 8 + t];
                afr[i][0] = p[0];
                afr[i][1] = p[8 * SA];
                afr[i][2] = p[4];
                afr[i][3] = p[8 * SA + 4];
            }
            unsigned bfr[4][2];
#pragma unroll
            for (int j = 0; j < 4; j++) {
                const unsigned* p =
                    &Bs[buf][(wn * 32 + j * 8 + g) * SA + ks * 8 + t];
                bfr[j][0] = p[0];
                bfr[j][1] = p[4];
            }
#pragma unroll
            for (int i = 0; i < 4; i++)
#pragma unroll
                for (int j = 0; j < 4; j++)
                    mma_tf32(acc[i][j][0], acc[i][j][1], acc[i][j][2], acc[i][j][3],
                             afr[i][0], afr[i][1], afr[i][2], afr[i][3],
                             bfr[j][0], bfr[j][1]);
        }

        if (kt < 63) {
            const int nb = buf ^ 1;
            uint4 u;
            u.x = f2tf(va0.x); u.y = f2tf(va0.y); u.z = f2tf(va0.z); u.w = f2tf(va0.w);
            *(uint4*)&As[nb][r0 * SA + c4] = u;
            u.x = f2tf(va1.x); u.y = f2tf(va1.y); u.z = f2tf(va1.z); u.w = f2tf(va1.w);
            *(uint4*)&As[nb][(r0 + 64) * SA + c4] = u;
            u.x = f2tf(vb0.x); u.y = f2tf(vb0.y); u.z = f2tf(vb0.z); u.w = f2tf(vb0.w);
            *(uint4*)&Bs[nb][r0 * SA + c4] = u;
            u.x = f2tf(vb1.x); u.y = f2tf(vb1.y); u.z = f2tf(vb1.z); u.w = f2tf(vb1.w);
            *(uint4*)&Bs[nb][(r0 + 64) * SA + c4] = u;
            __syncthreads();
        }
    }

#pragma unroll
    for (int i = 0; i < 4; i++) {
        const int mlo = m0 + wm * 64 + i * 16 + g;
#pragma unroll
        for (int j = 0; j < 4; j++) {
            const int col = n0 + wn * 32 + j * 8 + 2 * t;
            if (EPI == 1) {
                const float2 bb = *(const float2*)&bias[col];
                float2 o0 = {acc[i][j][0] + bb.x, acc[i][j][1] + bb.y};
                float2 o1 = {acc[i][j][2] + bb.x, acc[i][j][3] + bb.y};
                *(float2*)&out[(size_t)mlo * 1024 + col] = o0;
                *(float2*)&out[(size_t)(mlo + 8) * 1024 + col] = o1;
            } else {
                const int part = col >> 10;
                const int h = (col >> 6) & (H_ - 1);
                const int d = col & (D_ - 1);
                const int f = d >> 1;
#pragma unroll
                for (int rr = 0; rr < 2; rr++) {
                    const int m = mlo + rr * 8;
                    const int b = m >> 11;
                    const int nr = m & (N_ - 1);
                    const float v0 = acc[i][j][rr * 2 + 0];
                    const float v1 = acc[i][j][rr * 2 + 1];
                    const size_t off =
                        (((size_t)(b * H_ + h) * N_) + nr) * D_ + d;
                    if (part == 2) {
                        float2 o = {v0, v1};
                        *(float2*)&g_v[off] = o;
                    } else {
                        const float c = fcos[nr * 32 + f];
                        const float s = fsin[nr * 32 + f];
                        float2 o = {v0 * c - v1 * s, v0 * s + v1 * c};
                        float* dst = (part == 0) ? g_q : g_k;
                        *(float2*)&dst[off] = o;
                    }
                }
            }
        }
    }
}

// ---------------------------------------------------------------------------
// Flash attention, tf32 HMMA, 64-key tiles, latency-hidden staging.
// K: double-buffered cp.async, XOR-swizzled [key][d] stride 64 (2 x 16KB).
//    chunk16B position = chunk ^ (key & 7). Second B-operand lives at
//    chunk ^ 1 -> byte offset XOR 16.
// V: LDG->regs at tile top, STS AFTER S-GEMM (latency hidden), swizzled
//    Vt[d][key]: chunk position = (key>>2) ^ (d & 7). Total smem = 48KB.
// ---------------------------------------------------------------------------
__global__ __launch_bounds__(256, 2) void attn_tc_kernel()
{
    __shared__ __align__(16) float Kbuf[2][64 * 64];
    __shared__ __align__(16) float Vt[64 * 64];

    const int tid = threadIdx.x;
    const int w = tid >> 5;
    const int lane = tid & 31;
    const int g = lane >> 2;
    const int t = lane & 3;

    const int bh = blockIdx.y;
    const int q0 = blockIdx.x * 128;
    const int qlo = q0 + w * 16 + g;

    const float* qb = g_q + (size_t)bh * N_ * D_;
    const float* kb = g_k + (size_t)bh * N_ * D_;
    const float* vb = g_v + (size_t)bh * N_ * D_;

    // Q A-fragments, pre-scaled (x0.125 exact), register-resident (R4 numerics).
    unsigned qf[8][4];
#pragma unroll
    for (int s = 0; s < 8; s++) {
        const float* plo = qb + (size_t)qlo * D_ + s * 8 + t;
        const float* phi = plo + 8 * D_;
        qf[s][0] = __float_as_uint(plo[0] * SCALE);
        qf[s][1] = __float_as_uint(phi[0] * SCALE);
        qf[s][2] = __float_as_uint(plo[4] * SCALE);
        qf[s][3] = __float_as_uint(phi[4] * SCALE);
    }

    float oacc[8][4];
#pragma unroll
    for (int j = 0; j < 8; j++)
#pragma unroll
        for (int q = 0; q < 4; q++) oacc[j][q] = 0.f;
    float m_lo = -CUDART_INF_F, m_hi = -CUDART_INF_F;
    float l_lo = 0.f, l_hi = 0.f;

    // K producer mapping: row pr (0..63, 256B), chunks pc..pc+3 (16B each)
    const int pr = tid >> 2;
    const int pc = (tid & 3) * 4;
    unsigned kdst[4];
#pragma unroll
    for (int c = 0; c < 4; c++) {
        const unsigned sw = (unsigned)((pc + c) ^ (pr & 7));
        kdst[c] = (unsigned)__cvta_generic_to_shared(
                      (const char*)Kbuf + (unsigned)pr * 256 + sw * 16);
    }
    const char* kgm = (const char*)(kb + (size_t)pr * 64) + pc * 16;

    // V producer mapping (r0=key, c4=d base)
    const int r0 = pr;
    const int c4 = (tid & 3) * 4;

    const int src_lo = (lane & 28) | (t >> 1);
    const int src_hi = src_lo + 2;
    const bool odd = t & 1;

    // prologue: K[0] -> Kbuf[0]
#pragma unroll
    for (int c = 0; c < 4; c++) cp_async16(kdst[c], kgm + c * 16);
    cp_commit();

    for (int it = 0; it < 32; it++) {
        asm volatile("cp.async.wait_group 0;");
        __syncthreads();   // K[it] visible; previous tile fully consumed

        const char* Kc = (const char*)Kbuf[it & 1];

        if (it < 31) {     // prefetch K[it+1] — overlaps the whole tile
            const unsigned so = (unsigned)((it + 1) & 1) * 16384u;
            const char* src = kgm + (size_t)(it + 1) * 16384;
#pragma unroll
            for (int c = 0; c < 4; c++) cp_async16(kdst[c] + so, src + c * 16);
            cp_commit();
        }

        // V[it] LDG into regs — latency hidden by the S-GEMM below
        float4 vv[4];
#pragma unroll
        for (int ch = 0; ch < 4; ch++) {
            const int d = c4 + ch * 16;
            vv[ch] = *(const float4*)(vb + ((size_t)it * 64 + r0) * 64 + d);
        }

        // S = Q @ K^T : swizzled K reads; operand1 at chunk^1 (offset ^ 16)
        float sacc[8][4];
#pragma unroll
        for (int j = 0; j < 8; j++)
#pragma unroll
            for (int q = 0; q < 4; q++) sacc[j][q] = 0.f;
#pragma unroll
        for (int s = 0; s < 8; s++) {
            const unsigned soff = (unsigned)(((2 * s) ^ g) << 4) + (unsigned)(t << 2);
#pragma unroll
            for (int j = 0; j < 8; j++) {
                const unsigned rbase = (unsigned)(8 * j + g) << 8;
                const char* p0 = Kc + rbase + soff;
                const char* p1 = Kc + rbase + (soff ^ 16u);
                mma_tf32(sacc[j][0], sacc[j][1], sacc[j][2], sacc[j][3],
                         qf[s][0], qf[s][1], qf[s][2], qf[s][3],
                         __float_as_uint(*(const float*)p0),
                         __float_as_uint(*(const float*)p1));
            }
        }

        // STS V (transpose into swizzled Vt) — vv regs have landed by now
#pragma unroll
        for (int ch = 0; ch < 4; ch++) {
            const int d = c4 + ch * 16;
            const float vr[4] = {vv[ch].x, vv[ch].y, vv[ch].z, vv[ch].w};
#pragma unroll
            for (int i = 0; i < 4; i++) {
                const int row = d + i;
                const unsigned sw = (unsigned)((r0 >> 2) ^ (row & 7));
                *(float*)((char*)Vt + (unsigned)row * 256 + sw * 16 +
                          (unsigned)(r0 & 3) * 4) = vr[i];
            }
        }

        // Online softmax (independent of Vt; overlaps STS drain)
        float mx_lo = -CUDART_INF_F, mx_hi = -CUDART_INF_F;
#pragma unroll
        for (int j = 0; j < 8; j++) {
            mx_lo = fmaxf(mx_lo, fmaxf(sacc[j][0], sacc[j][1]));
            mx_hi = fmaxf(mx_hi, fmaxf(sacc[j][2], sacc[j][3]));
        }
#pragma unroll
        for (int off = 2; off >= 1; off >>= 1) {
            mx_lo = fmaxf(mx_lo, __shfl_xor_sync(0xffffffffu, mx_lo, off));
            mx_hi = fmaxf(mx_hi, __shfl_xor_sync(0xffffffffu, mx_hi, off));
        }
        const float mn_lo = fmaxf(m_lo, mx_lo);
        const float mn_hi = fmaxf(m_hi, mx_hi);
        const float al_lo = __expf(m_lo - mn_lo);
        const float al_hi = __expf(m_hi - mn_hi);
        float rs_lo = 0.f, rs_hi = 0.f;
#pragma unroll
        for (int j = 0; j < 8; j++) {
            sacc[j][0] = __expf(sacc[j][0] - mn_lo);
            sacc[j][1] = __expf(sacc[j][1] - mn_lo);
            sacc[j][2] = __expf(sacc[j][2] - mn_hi);
            sacc[j][3] = __expf(sacc[j][3] - mn_hi);
            rs_lo += sacc[j][0] + sacc[j][1];
            rs_hi += sacc[j][2] + sacc[j][3];
        }
#pragma unroll
        for (int off = 2; off >= 1; off >>= 1) {
            rs_lo += __shfl_xor_sync(0xffffffffu, rs_lo, off);
            rs_hi += __shfl_xor_sync(0xffffffffu, rs_hi, off);
        }
        l_lo = l_lo * al_lo + rs_lo;  m_lo = mn_lo;
        l_hi = l_hi * al_hi + rs_hi;  m_hi = mn_hi;
#pragma unroll
        for (int j = 0; j < 8; j++) {
            oacc[j][0] *= al_lo; oacc[j][1] *= al_lo;
            oacc[j][2] *= al_hi; oacc[j][3] *= al_hi;
        }

        __syncthreads();   // Vt visible to all

        // O += P @ V : C-frag -> A-frag via quad shfl; swizzled Vt reads,
        // operand1 at chunk^1 (offset ^ 16)
#pragma unroll
        for (int s = 0; s < 8; s++) {
            const float x0 = __shfl_sync(0xffffffffu, sacc[s][0], src_lo);
            const float x1 = __shfl_sync(0xffffffffu, sacc[s][1], src_lo);
            const float x2 = __shfl_sync(0xffffffffu, sacc[s][2], src_lo);
            const float x3 = __shfl_sync(0xffffffffu, sacc[s][3], src_lo);
            const float y0 = __shfl_sync(0xffffffffu, sacc[s][0], src_hi);
            const float y1 = __shfl_sync(0xffffffffu, sacc[s][1], src_hi);
            const float y2 = __shfl_sync(0xffffffffu, sacc[s][2], src_hi);
            const float y3 = __shfl_sync(0xffffffffu, sacc[s][3], src_hi);
            const unsigned a0 = f2tf(odd ? x1 : x0);
            const unsigned a1 = f2tf(odd ? x3 : x2);
            const unsigned a2 = f2tf(odd ? y1 : y0);
            const unsigned a3 = f2tf(odd ? y3 : y2);
            const unsigned soff = (unsigned)(((2 * s) ^ g) << 4) + (unsigned)(t << 2);
#pragma unroll
            for (int jd = 0; jd < 8; jd++) {
                const unsigned rbase = (unsigned)(8 * jd + g) << 8;
                const char* p0 = (const char*)Vt + rbase + soff;
                const char* p1 = (const char*)Vt + rbase + (soff ^ 16u);
                mma_tf32(oacc[jd][0], oacc[jd][1], oacc[jd][2], oacc[jd][3],
                         a0, a1, a2, a3,
                         __float_as_uint(*(const float*)p0),
                         __float_as_uint(*(const float*)p1));
            }
        }
    }

    // Normalize and write to g_ao [B*N, C]
    const float inv_lo = 1.0f / l_lo;
    const float inv_hi = 1.0f / l_hi;
    const int b = bh >> 4;
    const int h = bh & (H_ - 1);
#pragma unroll
    for (int jd = 0; jd < 8; jd++) {
        const int col = h * D_ + jd * 8 + 2 * t;
        float2 o0 = {oacc[jd][0] * inv_lo, oacc[jd][1] * inv_lo};
        float2 o1 = {oacc[jd][2] * inv_hi, oacc[jd][3] * inv_hi};
        *(float2*)&g_ao[((size_t)(b * N_ + qlo)) * C_ + col] = o0;
        *(float2*)&g_ao[((size_t)(b * N_ + qlo + 8)) * C_ + col] = o1;
    }
}

// ---------------------------------------------------------------------------
extern "C" void kernel_launch(void* const* d_in, const int* in_sizes, int n_in,
                              void* d_out, int out_size)
{
    (void)in_sizes; (void)n_in; (void)out_size;
    const float* x      = (const float*)d_in[0];
    const float* qkv_w  = (const float*)d_in[1];
    const float* proj_w = (const float*)d_in[2];
    const float* proj_b = (const float*)d_in[3];
    const float* fcos   = (const float*)d_in[4];
    const float* fsin   = (const float*)d_in[5];
    float* out = (float*)d_out;

    // 1) QKV GEMM (R4-exact tf32) + RoPE scatter
    gemm_tf32_kernel<0><<<dim3(3 * C_ / 128, M_ / 128), 256>>>(
        x, qkv_w, fcos, fsin, nullptr, nullptr);
    // 2) Flash attention (tf32 HMMA, latency-hidden K/V staging)
    attn_tc_kernel<<<dim3(N_ / 128, B_ * H_), 256>>>();
    // 3) Output projection (R4-exact tf32) + bias
    gemm_tf32_kernel<1><<<dim3(C_ / 128, M_ / 128), 256>>>(
        nullptr, proj_w, nullptr, nullptr, proj_b, out);
}